// round 8
// baseline (speedup 1.0000x reference)
#include <cuda_runtime.h>
#include <cuda_fp16.h>
#include <cstdint>
#include <cstddef>

// Problem dims
#define G_N 8
#define D_N 1024
#define H_N 2048
#define O_N 1024
#define B_N 8192   // rows per group (65536 / 8)

// ---------------- scratch (static device arrays; allocation-free) ----------------
__device__ __align__(1024) __half g_xh  [(size_t)65536 * 1024];     // x fp16, group-major [g][b][d]
__device__ __align__(1024) __half g_wgh [(size_t)8 * 2048 * 1024];  // Wg fp16 [g][h][d]
__device__ __align__(1024) __half g_wuh [(size_t)8 * 2048 * 1024];  // Wu fp16 [g][h][d]
__device__ __align__(1024) __half g_wdh [(size_t)8 * 1024 * 2048];  // Wd fp16 [g][o][h]
__device__ __align__(1024) __half g_hid [(size_t)65536 * 2048];     // hidden fp16 [g][b][h]

// ---------------- helpers ----------------
__device__ __forceinline__ uint32_t smem_u32(const void* p) {
    return (uint32_t)__cvta_generic_to_shared(p);
}

// 8KB tile = 128 rows x 32 halves (64B rows). Swizzle 16B chunks:
// phys(r, c) = r*64 + ((c ^ ((r>>1)&3)) * 16), c in [0,4)
__device__ __forceinline__ uint32_t swz(int r, int c) {
    return (uint32_t)(r * 64 + ((c ^ ((r >> 1) & 3)) << 4));
}

__device__ __forceinline__ void cpa16(uint32_t s, const void* g) {
    asm volatile("cp.async.cg.shared.global [%0], [%1], 16;" :: "r"(s), "l"(g));
}
__device__ __forceinline__ void cpa_commit() { asm volatile("cp.async.commit_group;" ::: "memory"); }
__device__ __forceinline__ void cpa_wait1()  { asm volatile("cp.async.wait_group 1;"  ::: "memory"); }
__device__ __forceinline__ void cpa_wait0()  { asm volatile("cp.async.wait_group 0;"  ::: "memory"); }

__device__ __forceinline__ void ldsm_x4(uint32_t& r0, uint32_t& r1, uint32_t& r2, uint32_t& r3,
                                        uint32_t addr) {
    asm volatile("ldmatrix.sync.aligned.m8n8.x4.shared.b16 {%0,%1,%2,%3}, [%4];"
                 : "=r"(r0), "=r"(r1), "=r"(r2), "=r"(r3) : "r"(addr));
}
__device__ __forceinline__ void ldsm_x2(uint32_t& r0, uint32_t& r1, uint32_t addr) {
    asm volatile("ldmatrix.sync.aligned.m8n8.x2.shared.b16 {%0,%1}, [%2];"
                 : "=r"(r0), "=r"(r1) : "r"(addr));
}

__device__ __forceinline__ void mma16816(float* c, const uint32_t* a, const uint32_t* b) {
    asm volatile(
        "mma.sync.aligned.m16n8k16.row.col.f32.f16.f16.f32 "
        "{%0,%1,%2,%3}, {%4,%5,%6,%7}, {%8,%9}, {%0,%1,%2,%3};"
        : "+f"(c[0]), "+f"(c[1]), "+f"(c[2]), "+f"(c[3])
        : "r"(a[0]), "r"(a[1]), "r"(a[2]), "r"(a[3]), "r"(b[0]), "r"(b[1]));
}

__device__ __forceinline__ float silu_f(float v) {
    return __fdividef(v, 1.0f + __expf(-v));
}

// ---------------- pass 0: conversions ----------------
__global__ void cvt_x_kernel(const float* __restrict__ x) {
    size_t i = ((size_t)blockIdx.x * 256 + threadIdx.x) * 4;
    float4 v = *reinterpret_cast<const float4*>(x + i);
    int row = (int)(i >> 10);
    int col = (int)(i & 1023);
    int g = row & 7, b = row >> 3;
    __half2 h0 = __floats2half2_rn(v.x, v.y);
    __half2 h1 = __floats2half2_rn(v.z, v.w);
    __half2* d = reinterpret_cast<__half2*>(g_xh + (((size_t)(g * B_N + b)) << 10) + col);
    d[0] = h0; d[1] = h1;
}

__global__ void cvt_w_kernel(const float* __restrict__ s, int which) {
    size_t i = ((size_t)blockIdx.x * 256 + threadIdx.x) * 4;
    __half* dst = (which == 0) ? g_wgh : (which == 1) ? g_wuh : g_wdh;
    float4 v = *reinterpret_cast<const float4*>(s + i);
    __half2 h0 = __floats2half2_rn(v.x, v.y);
    __half2 h1 = __floats2half2_rn(v.z, v.w);
    __half2* d = reinterpret_cast<__half2*>(dst + i);
    d[0] = h0; d[1] = h1;
}

// ---------------- pass 1: FUSED gate+up GEMM + SwiGLU ----------------
// CTA tile 128x128, BK=32. 8 warps as 2(M)x4(N); warp tile 64x32.
// A tile shared by both B matrices (Wg, Wu). gate/up accumulated simultaneously
// in registers; SwiGLU fused in epilogue -> g_hid fp16. No gate round-trip.
__global__ void __launch_bounds__(256, 1) gemm_gu_kernel() {
    __shared__ __align__(1024) __half smA [2][128 * 32];
    __shared__ __align__(1024) __half smBg[2][128 * 32];
    __shared__ __align__(1024) __half smBu[2][128 * 32];

    int tid = threadIdx.x, l = tid & 31, wid = tid >> 5;
    int wm = wid & 1, wn = wid >> 1;
    int g = blockIdx.z, m0 = blockIdx.y * 128, n0 = blockIdx.x * 128;

    const __half* A  = g_xh  + ((size_t)g * B_N + m0) * D_N;
    const __half* Bg = g_wgh + ((size_t)g * H_N + n0) * D_N;
    const __half* Bu = g_wuh + ((size_t)g * H_N + n0) * D_N;

    uint32_t sAu[2]  = { smem_u32(smA[0]),  smem_u32(smA[1])  };
    uint32_t sBgu[2] = { smem_u32(smBg[0]), smem_u32(smBg[1]) };
    uint32_t sBuu[2] = { smem_u32(smBu[0]), smem_u32(smBu[1]) };

    float accG[4][4][4], accU[4][4][4];
    #pragma unroll
    for (int i = 0; i < 4; i++)
        #pragma unroll
        for (int j = 0; j < 4; j++)
            #pragma unroll
            for (int q = 0; q < 4; q++) { accG[i][j][q] = 0.0f; accU[i][j][q] = 0.0f; }

    auto load_tiles = [&](int kc, int s) {
        int k0 = kc * 32;
        #pragma unroll
        for (int i = 0; i < 2; i++) {
            int linear = tid + i * 256;                 // 0..511
            int r = linear >> 2, c = linear & 3;
            uint32_t so = swz(r, c);
            size_t go = (size_t)r * D_N + k0 + c * 8;
            cpa16(sAu[s]  + so, A  + go);
            cpa16(sBgu[s] + so, Bg + go);
            cpa16(sBuu[s] + so, Bu + go);
        }
    };

    const int NKC = D_N / 32;   // 32
    load_tiles(0, 0);
    cpa_commit();

    for (int kc = 0; kc < NKC; kc++) {
        int s = kc & 1;
        if (kc + 1 < NKC) { load_tiles(kc + 1, s ^ 1); cpa_commit(); cpa_wait1(); }
        else              { cpa_wait0(); }
        __syncthreads();

        #pragma unroll
        for (int ks = 0; ks < 2; ks++) {
            uint32_t af[4][4], bg[4][2], bu[4][2];
            #pragma unroll
            for (int i = 0; i < 4; i++) {
                int r = wm * 64 + i * 16 + (l & 15);
                int c = ks * 2 + (l >> 4);
                ldsm_x4(af[i][0], af[i][1], af[i][2], af[i][3], sAu[s] + swz(r, c));
            }
            #pragma unroll
            for (int j = 0; j < 4; j++) {
                int r = wn * 32 + j * 8 + (l & 7);
                int c = ks * 2 + ((l >> 3) & 1);
                uint32_t so = swz(r, c);
                ldsm_x2(bg[j][0], bg[j][1], sBgu[s] + so);
                ldsm_x2(bu[j][0], bu[j][1], sBuu[s] + so);
            }
            #pragma unroll
            for (int i = 0; i < 4; i++)
                #pragma unroll
                for (int j = 0; j < 4; j++) {
                    mma16816(accG[i][j], af[i], bg[j]);
                    mma16816(accU[i][j], af[i], bu[j]);
                }
        }
        __syncthreads();
    }

    // epilogue: silu(gate) * up -> fp16 hidden (registers only, no global gate)
    int rq = l >> 2;          // 0..7
    int cq = 2 * (l & 3);     // 0,2,4,6
    #pragma unroll
    for (int i = 0; i < 4; i++) {
        int mrow0 = m0 + wm * 64 + i * 16 + rq;
        #pragma unroll
        for (int j = 0; j < 4; j++) {
            int col = n0 + wn * 32 + j * 8 + cq;
            float h0 = silu_f(accG[i][j][0]) * accU[i][j][0];
            float h1 = silu_f(accG[i][j][1]) * accU[i][j][1];
            float h2 = silu_f(accG[i][j][2]) * accU[i][j][2];
            float h3 = silu_f(accG[i][j][3]) * accU[i][j][3];
            __half2* p0 = reinterpret_cast<__half2*>(
                g_hid + ((size_t)g * B_N + mrow0) * H_N + col);
            __half2* p1 = reinterpret_cast<__half2*>(
                g_hid + ((size_t)g * B_N + mrow0 + 8) * H_N + col);
            *p0 = __floats2half2_rn(h0, h1);
            *p1 = __floats2half2_rn(h2, h3);
        }
    }
}

// ---------------- pass 2: down projection ----------------
// CTA tile 128x128, BK=32, K=2048. out fp32 at interleaved row b*8+g.
__global__ void __launch_bounds__(256) gemm_d_kernel(float* __restrict__ out) {
    __shared__ __align__(1024) __half smA[2][128 * 32];
    __shared__ __align__(1024) __half smB[2][128 * 32];

    int tid = threadIdx.x, l = tid & 31, wid = tid >> 5;
    int wm = wid & 1, wn = wid >> 1;
    int g = blockIdx.z, m0 = blockIdx.y * 128, n0 = blockIdx.x * 128;

    const __half* A = g_hid + ((size_t)g * B_N + m0) * H_N;
    const __half* B = g_wdh + ((size_t)g * O_N + n0) * H_N;

    uint32_t sAu[2] = { smem_u32(smA[0]), smem_u32(smA[1]) };
    uint32_t sBu[2] = { smem_u32(smB[0]), smem_u32(smB[1]) };

    float acc[4][4][4];
    #pragma unroll
    for (int i = 0; i < 4; i++)
        #pragma unroll
        for (int j = 0; j < 4; j++)
            #pragma unroll
            for (int q = 0; q < 4; q++) acc[i][j][q] = 0.0f;

    auto load_tiles = [&](int kc, int s) {
        int k0 = kc * 32;
        #pragma unroll
        for (int i = 0; i < 2; i++) {
            int linear = tid + i * 256;
            int r = linear >> 2, c = linear & 3;
            uint32_t so = swz(r, c);
            size_t go = (size_t)r * H_N + k0 + c * 8;
            cpa16(sAu[s] + so, A + go);
            cpa16(sBu[s] + so, B + go);
        }
    };

    const int NKC = H_N / 32;   // 64
    load_tiles(0, 0);
    cpa_commit();

    for (int kc = 0; kc < NKC; kc++) {
        int s = kc & 1;
        if (kc + 1 < NKC) { load_tiles(kc + 1, s ^ 1); cpa_commit(); cpa_wait1(); }
        else              { cpa_wait0(); }
        __syncthreads();

        #pragma unroll
        for (int ks = 0; ks < 2; ks++) {
            uint32_t af[4][4], bf[4][2];
            #pragma unroll
            for (int i = 0; i < 4; i++) {
                int r = wm * 64 + i * 16 + (l & 15);
                int c = ks * 2 + (l >> 4);
                ldsm_x4(af[i][0], af[i][1], af[i][2], af[i][3], sAu[s] + swz(r, c));
            }
            #pragma unroll
            for (int j = 0; j < 4; j++) {
                int r = wn * 32 + j * 8 + (l & 7);
                int c = ks * 2 + ((l >> 3) & 1);
                ldsm_x2(bf[j][0], bf[j][1], sBu[s] + swz(r, c));
            }
            #pragma unroll
            for (int i = 0; i < 4; i++)
                #pragma unroll
                for (int j = 0; j < 4; j++)
                    mma16816(acc[i][j], af[i], bf[j]);
        }
        __syncthreads();
    }

    int rq = l >> 2;
    int cq = 2 * (l & 3);
    #pragma unroll
    for (int i = 0; i < 4; i++) {
        int mrow0 = m0 + wm * 64 + i * 16 + rq;
        #pragma unroll
        for (int j = 0; j < 4; j++) {
            int col = n0 + wn * 32 + j * 8 + cq;
            float2* p0 = reinterpret_cast<float2*>(
                out + ((size_t)(mrow0 * G_N + g)) * O_N + col);
            float2* p1 = reinterpret_cast<float2*>(
                out + ((size_t)((mrow0 + 8) * G_N + g)) * O_N + col);
            *p0 = make_float2(acc[i][j][0], acc[i][j][1]);
            *p1 = make_float2(acc[i][j][2], acc[i][j][3]);
        }
    }
}

// ---------------- launcher ----------------
extern "C" void kernel_launch(void* const* d_in, const int* in_sizes, int n_in,
                              void* d_out, int out_size) {
    (void)in_sizes; (void)n_in; (void)out_size;
    const float* x  = (const float*)d_in[0];
    const float* Wg = (const float*)d_in[1];
    const float* Wu = (const float*)d_in[2];
    const float* Wd = (const float*)d_in[3];
    float* out = (float*)d_out;

    cvt_x_kernel<<<65536, 256>>>(x);
    cvt_w_kernel<<<16384, 256>>>(Wg, 0);
    cvt_w_kernel<<<16384, 256>>>(Wu, 1);
    cvt_w_kernel<<<16384, 256>>>(Wd, 2);

    gemm_gu_kernel<<<dim3(16, 64, 8), 256>>>();        // fused gate+up+SwiGLU
    gemm_d_kernel<<<dim3(8, 64, 8), 256>>>(out);       // down proj
}